// round 3
// baseline (speedup 1.0000x reference)
#include <cuda_runtime.h>
#include <math.h>

// Problem constants
#define BB 4
#define CC 128
#define NN 16384
#define MM 4096
#define KK 16
#define G  16
#define NC (G*G*G)       // 4096 cells
#define SSTRIDE 4104     // padded (NC+1) rounded to int4 multiple

// Scratch (allocation-free rule: __device__ globals)
__device__ float  g_featT[BB * NN * CC];    // (B,N,C)
__device__ float  g_pooled[BB * MM * CC];   // (B,M,C)
__device__ int    g_knn[BB * NN * 3];
__device__ float  g_wgt[BB * NN * 3];

// Uniform-grid structures (per batch). Counters fused for one memset.
__device__ int    g_cnt[2 * BB * NC];       // [0..BB*NC): supports, rest: queries
__device__ int    g_sstart[BB * SSTRIDE];
__device__ int    g_cur[2 * BB * NC];       // scatter cursors (supports, queries)
__device__ float4 g_spts[BB * MM];          // x,y,z,|s|^2  (cell-sorted)
__device__ int    g_sidx[BB * MM];          // original support index
__device__ float4 g_qpts[BB * NN];          // x,y,z,bitcast(query idx) (cell-sorted)
__device__ int    g_qstart[BB * (NC + 1)];  // query prefix (scatter only)

__device__ __forceinline__ int cellof(float v) {
    int c = (int)(v * (float)G);
    return c < 0 ? 0 : (c > G - 1 ? G - 1 : c);
}

// ---------------- grid build ----------------
__global__ void k_count(const float* __restrict__ xyzs, const float* __restrict__ xyzq) {
    int t = blockIdx.x * blockDim.x + threadIdx.x;
    if (t < BB * MM) {
        int b = t >> 12, m = t & (MM - 1);
        const float* p = xyzs + (size_t)(b * MM + m) * 3;
        int c = (cellof(p[2]) * G + cellof(p[1])) * G + cellof(p[0]);
        atomicAdd(&g_cnt[b * NC + c], 1);
    } else if (t < BB * (MM + NN)) {
        int u = t - BB * MM;
        int b = u >> 14, n = u & (NN - 1);
        const float* p = xyzq + (size_t)(b * NN + n) * 3;
        int c = (cellof(p[2]) * G + cellof(p[1])) * G + cellof(p[0]);
        atomicAdd(&g_cnt[BB * NC + b * NC + c], 1);
    }
}

// One block per (batch, which). 1024 threads, 4 cells/thread.
__global__ void k_scan() {
    __shared__ int ssum[1024];
    int which = blockIdx.x & 1;          // 0 = supports, 1 = queries
    int b = blockIdx.x >> 1;
    int* cnt = g_cnt + which * BB * NC + b * NC;
    int* cur = g_cur + which * BB * NC + b * NC;
    int t = threadIdx.x;
    int4 v = ((const int4*)cnt)[t];
    int s = v.x + v.y + v.z + v.w;
    ssum[t] = s;
    __syncthreads();
    for (int off = 1; off < 1024; off <<= 1) {
        int y = (t >= off) ? ssum[t - off] : 0;
        __syncthreads();
        ssum[t] += y;
        __syncthreads();
    }
    int e = ssum[t] - s;   // exclusive prefix
    if (which == 0) {
        int* start = g_sstart + b * SSTRIDE;
        start[4*t+0] = e; cur[4*t+0] = e; e += v.x;
        start[4*t+1] = e; cur[4*t+1] = e; e += v.y;
        start[4*t+2] = e; cur[4*t+2] = e; e += v.z;
        start[4*t+3] = e; cur[4*t+3] = e;
        if (t == 1023) { start[NC] = ssum[1023]; start[NC+1]=start[NC+2]=start[NC+3]=ssum[1023]; }
    } else {
        cur[4*t+0] = e; e += v.x;
        cur[4*t+1] = e; e += v.y;
        cur[4*t+2] = e; e += v.z;
        cur[4*t+3] = e;
    }
}

__global__ void k_scatter(const float* __restrict__ xyzs, const float* __restrict__ xyzq) {
    int t = blockIdx.x * blockDim.x + threadIdx.x;
    if (t < BB * MM) {
        int b = t >> 12, m = t & (MM - 1);
        const float* p = xyzs + (size_t)(b * MM + m) * 3;
        float x = p[0], y = p[1], z = p[2];
        int c = (cellof(z) * G + cellof(y)) * G + cellof(x);
        int pos = atomicAdd(&g_cur[b * NC + c], 1);
        g_spts[b * MM + pos] = make_float4(x, y, z, x*x + y*y + z*z);
        g_sidx[b * MM + pos] = m;
    } else if (t < BB * (MM + NN)) {
        int u = t - BB * MM;
        int b = u >> 14, n = u & (NN - 1);
        const float* p = xyzq + (size_t)(b * NN + n) * 3;
        float x = p[0], y = p[1], z = p[2];
        int c = (cellof(z) * G + cellof(y)) * G + cellof(x);
        int pos = atomicAdd(&g_cur[BB * NC + b * NC + c], 1);
        g_qpts[b * NN + pos] = make_float4(x, y, z, __int_as_float(n));
    }
}

// ---------------- Kernel A: transpose feature (B,C,N) -> (B,N,C) ----------------
__global__ void transpose_kernel(const float* __restrict__ feat) {
    __shared__ float tile[32][33];
    int b  = blockIdx.z;
    int n0 = blockIdx.x * 32;
    int c0 = blockIdx.y * 32;
    int tx = threadIdx.x, ty = threadIdx.y;   // 32 x 8
    const float* fb = feat + (size_t)b * CC * NN;
    #pragma unroll
    for (int i = 0; i < 32; i += 8)
        tile[ty + i][tx] = fb[(size_t)(c0 + ty + i) * NN + n0 + tx];
    __syncthreads();
    float* ft = g_featT + (size_t)b * NN * CC;
    #pragma unroll
    for (int i = 0; i < 32; i += 8)
        ft[(size_t)(n0 + ty + i) * CC + c0 + tx] = tile[tx][ty + i];
}

// ---------------- Kernel B: pooled[b,m,c] = max_k featT[b, idx[b,m,k], c] ----------------
// One warp per m; each lane owns 4 channels (float4). 16 independent 512B row reads.
__global__ __launch_bounds__(256) void pool_kernel(const int* __restrict__ pool_idx) {
    int b    = blockIdx.y;
    int m    = blockIdx.x * 8 + (threadIdx.x >> 5);
    int lane = threadIdx.x & 31;
    const int* ip = pool_idx + ((size_t)b * MM + m) * KK;
    int myidx = (lane < KK) ? ip[lane] : 0;
    const float* fb = g_featT + (size_t)b * NN * CC;
    float4 v = make_float4(-INFINITY, -INFINITY, -INFINITY, -INFINITY);
    #pragma unroll
    for (int k = 0; k < KK; k++) {
        int id = __shfl_sync(0xffffffffu, myidx, k);
        float4 f = ((const float4*)(fb + (size_t)id * CC))[lane];
        v.x = fmaxf(v.x, f.x); v.y = fmaxf(v.y, f.y);
        v.z = fmaxf(v.z, f.z); v.w = fmaxf(v.w, f.w);
    }
    ((float4*)(g_pooled + ((size_t)b * MM + m) * CC))[lane] = v;
}

// ---------------- Kernel C: exact 3-NN via uniform grid, expanding shells ----------------
// SMEM: spts float4[4096] (64KB) | sstart int[4104] | sidx int[4096]
#define KNN_SMEM (65536 + SSTRIDE*4 + 16384)

__global__ __launch_bounds__(256) void knn_kernel() {
    extern __shared__ char sh[];
    float4* spts   = (float4*)sh;
    int*    sstart = (int*)(sh + 65536);
    int*    sidx   = (int*)(sh + 65536 + SSTRIDE*4);

    int b = blockIdx.y;
    // cooperative smem fill (vectorized)
    for (int i = threadIdx.x; i < MM; i += 256)
        spts[i] = g_spts[b * MM + i];
    {
        const int4* src = (const int4*)(g_sidx + b * MM);
        int4* dst = (int4*)sidx;
        for (int i = threadIdx.x; i < MM / 4; i += 256) dst[i] = src[i];
        const int4* ss = (const int4*)(g_sstart + b * SSTRIDE);
        int4* sd = (int4*)sstart;
        for (int i = threadIdx.x; i < SSTRIDE / 4; i += 256) sd[i] = ss[i];
    }
    __syncthreads();

    int t = blockIdx.x * 256 + threadIdx.x;
    float4 qp = g_qpts[b * NN + t];
    float qx = qp.x, qy = qp.y, qz = qp.z;
    int   n  = __float_as_int(qp.w);
    float qn = qx*qx + qy*qy + qz*qz;
    int ci = cellof(qx), cj = cellof(qy), ck = cellof(qz);

    const float h = 1.0f / (float)G;
    float d0 = 1e30f, d1 = 1e30f, d2 = 1e30f;
    int   i0 = 0,     i1 = 0,     i2 = 0;

#define INSERT(dv, mv)                                              \
    do {                                                            \
        if ((dv) < d0)      { d2 = d1; i2 = i1; d1 = d0; i1 = i0;   \
                              d0 = (dv); i0 = (mv); }               \
        else if ((dv) < d1) { d2 = d1; i2 = i1;                     \
                              d1 = (dv); i1 = (mv); }               \
        else                { d2 = (dv); i2 = (mv); }               \
    } while (0)

#define SCAN_SPAN(cs, ce)                                           \
    for (int p = (cs); p < (ce); p++) {                             \
        float4 sp = spts[p];                                        \
        float dd = (qn + sp.w)                                      \
                 - 2.0f * (qx*sp.x + qy*sp.y + qz*sp.z);            \
        if (dd < d2) { int mi = sidx[p]; INSERT(dd, mi); }          \
    }

    for (int r = 0; r < G; r++) {
        int zlo = ck - r < 0 ? 0 : ck - r;
        int zhi = ck + r > G - 1 ? G - 1 : ck + r;
        for (int z = zlo; z <= zhi; z++) {
            bool zface = (z - ck == r) || (ck - z == r);
            int ylo = cj - r < 0 ? 0 : cj - r;
            int yhi = cj + r > G - 1 ? G - 1 : cj + r;
            for (int y = ylo; y <= yhi; y++) {
                bool face = zface || (y - cj == r) || (cj - y == r);
                int rowbase = (z * G + y) * G;
                if (face) {
                    int x0 = ci - r < 0 ? 0 : ci - r;
                    int x1 = ci + r > G - 1 ? G - 1 : ci + r;
                    int cs = sstart[rowbase + x0];
                    int ce = sstart[rowbase + x1 + 1];
                    SCAN_SPAN(cs, ce);
                } else {
                    int xa = ci - r;
                    if (xa >= 0) {
                        int cc0 = rowbase + xa;
                        SCAN_SPAN(sstart[cc0], sstart[cc0 + 1]);
                    }
                    int xb = ci + r;
                    if (xb <= G - 1) {
                        int cc1 = rowbase + xb;
                        SCAN_SPAN(sstart[cc1], sstart[cc1 + 1]);
                    }
                }
            }
        }
        // termination bound: any unscanned point is at true distance >= bound
        if (d2 < 1e30f) {
            float bl = (ci - r > 0)     ? qx - (float)(ci - r) * h     : 1e30f;
            float br = (ci + r < G - 1) ? (float)(ci + r + 1) * h - qx : 1e30f;
            float bd = (cj - r > 0)     ? qy - (float)(cj - r) * h     : 1e30f;
            float bu = (cj + r < G - 1) ? (float)(cj + r + 1) * h - qy : 1e30f;
            float bn = (ck - r > 0)     ? qz - (float)(ck - r) * h     : 1e30f;
            float bf = (ck + r < G - 1) ? (float)(ck + r + 1) * h - qz : 1e30f;
            float bound = fminf(fminf(fminf(bl, br), fminf(bd, bu)), fminf(bn, bf));
            if (bound * bound >= d2 + 1e-5f) break;
        }
    }
#undef SCAN_SPAN
#undef INSERT

    float r0 = 1.0f / (d0 + 1e-8f);
    float r1 = 1.0f / (d1 + 1e-8f);
    float r2 = 1.0f / (d2 + 1e-8f);
    float rs = 1.0f / (r0 + r1 + r2);
    int base = (b * NN + n) * 3;
    g_knn[base + 0] = i0;  g_knn[base + 1] = i1;  g_knn[base + 2] = i2;
    g_wgt[base + 0] = r0 * rs;  g_wgt[base + 1] = r1 * rs;  g_wgt[base + 2] = r2 * rs;
}

// ---------------- Kernel D: out[b,c,n] = sum_j pooled[b, knn_j(n), c] * w_j(n) ----------------
// Each lane owns channels {lane, lane+32, lane+64, lane+96}: conflict-free smem,
// fully coalesced gathers and stores.
__global__ __launch_bounds__(256) void interp_kernel(float* __restrict__ out) {
    __shared__ float tile[32][129];
    int b  = blockIdx.y;
    int n0 = blockIdx.x * 32;
    int t    = threadIdx.x;
    int lane = t & 31;
    int w    = t >> 5;     // 8 warps; warp w owns queries 4w..4w+3

    const float* pb = g_pooled + (size_t)b * MM * CC;

    #pragma unroll
    for (int i = 0; i < 4; i++) {
        int nl = w * 4 + i;
        int n  = n0 + nl;
        int base = (b * NN + n) * 3;
        int j0 = g_knn[base + 0], j1 = g_knn[base + 1], j2 = g_knn[base + 2];
        float w0 = g_wgt[base + 0], w1 = g_wgt[base + 1], w2 = g_wgt[base + 2];
        const float* p0 = pb + (size_t)j0 * CC;
        const float* p1 = pb + (size_t)j1 * CC;
        const float* p2 = pb + (size_t)j2 * CC;
        #pragma unroll
        for (int jj = 0; jj < 4; jj++) {
            int c = lane + 32 * jj;
            tile[nl][c] = w0 * p0[c] + w1 * p1[c] + w2 * p2[c];
        }
    }
    __syncthreads();

    float* ob = out + (size_t)b * CC * NN;
    #pragma unroll
    for (int i = 0; i < 16; i++) {
        int c = w + 8 * i;
        ob[(size_t)c * NN + n0 + lane] = tile[lane][c];
    }
}

extern "C" void kernel_launch(void* const* d_in, const int* in_sizes, int n_in,
                              void* d_out, int out_size) {
    const float* feature  = (const float*)d_in[0];
    const int*   pool_idx = (const int*)  d_in[1];
    const float* xyzq     = (const float*)d_in[2];
    const float* xyzs     = (const float*)d_in[3];
    float* out = (float*)d_out;

    // One-time setup (runs on the uncaptured correctness call; inert afterwards)
    static cudaStream_t s_side = nullptr;
    static cudaEvent_t  ev_fork = nullptr, ev_join = nullptr;
    static void* p_cnt = nullptr;
    if (!s_side) {
        cudaStreamCreateWithFlags(&s_side, cudaStreamNonBlocking);
        cudaEventCreateWithFlags(&ev_fork, cudaEventDisableTiming);
        cudaEventCreateWithFlags(&ev_join, cudaEventDisableTiming);
        cudaGetSymbolAddress(&p_cnt, g_cnt);
        cudaFuncSetAttribute(knn_kernel, cudaFuncAttributeMaxDynamicSharedMemorySize, KNN_SMEM);
    }

    // Fork: feature path on side stream, grid/knn path on default stream.
    cudaEventRecord(ev_fork, 0);
    cudaStreamWaitEvent(s_side, ev_fork, 0);

    // Side stream: transpose + pool
    transpose_kernel<<<dim3(NN / 32, CC / 32, BB), dim3(32, 8), 0, s_side>>>(feature);
    pool_kernel<<<dim3(MM / 8, BB), 256, 0, s_side>>>(pool_idx);
    cudaEventRecord(ev_join, s_side);

    // Default stream: grid build + knn
    cudaMemsetAsync(p_cnt, 0, sizeof(int) * 2 * BB * NC, 0);
    k_count<<<(BB * (MM + NN) + 255) / 256, 256>>>(xyzs, xyzq);
    k_scan<<<2 * BB, 1024>>>();
    k_scatter<<<(BB * (MM + NN) + 255) / 256, 256>>>(xyzs, xyzq);
    knn_kernel<<<dim3(NN / 256, BB), 256, KNN_SMEM>>>();

    // Join, then interpolation (needs pooled + knn)
    cudaStreamWaitEvent(0, ev_join, 0);
    interp_kernel<<<dim3(NN / 32, BB), 256>>>(out);
}

// round 5
// speedup vs baseline: 1.2489x; 1.2489x over previous
#include <cuda_runtime.h>
#include <math.h>

// Problem constants
#define BB 4
#define CC 128
#define NN 16384
#define MM 4096
#define KK 16
#define G  16
#define NC (G*G*G)       // 4096 cells
#define SSTRIDE 4104     // padded (NC+1) rounded to int4 multiple

// Scratch (allocation-free rule: __device__ globals)
__device__ float  g_featT[BB * NN * CC];    // (B,N,C)
__device__ float  g_pooled[BB * MM * CC];   // (B,M,C)
__device__ int    g_knn[BB * NN * 3];
__device__ float  g_wgt[BB * NN * 3];

// Uniform-grid structures (per batch). Counters fused for one memset.
__device__ int    g_cnt[2 * BB * NC];       // [0..BB*NC): supports, rest: queries
__device__ int    g_sstart[BB * SSTRIDE];
__device__ int    g_qstart[BB * NC];
__device__ int    g_cell[BB * (MM + NN)];   // cell id per point (supports then queries)
__device__ int    g_rank[BB * (MM + NN)];   // within-cell rank from count phase
__device__ float4 g_spts[BB * MM];          // x,y,z,|s|^2  (cell-sorted)
__device__ int    g_sidx[BB * MM];          // original support index
__device__ float4 g_qpts[BB * NN];          // x,y,z,bitcast(query idx) (cell-sorted)

__device__ __forceinline__ int cellof(float v) {
    int c = (int)(v * (float)G);
    return c < 0 ? 0 : (c > G - 1 ? G - 1 : c);
}

// ---------------- grid build ----------------
// Count + record (cellid, rank) so scatter needs no atomics.
__global__ void k_count(const float* __restrict__ xyzs, const float* __restrict__ xyzq) {
    int t = blockIdx.x * blockDim.x + threadIdx.x;
    if (t < BB * MM) {
        int b = t >> 12, m = t & (MM - 1);
        const float* p = xyzs + (size_t)(b * MM + m) * 3;
        int c = (cellof(p[2]) * G + cellof(p[1])) * G + cellof(p[0]);
        int r = atomicAdd(&g_cnt[b * NC + c], 1);
        g_cell[t] = c;  g_rank[t] = r;
    } else if (t < BB * (MM + NN)) {
        int u = t - BB * MM;
        int b = u >> 14;
        const float* p = xyzq + (size_t)u * 3;   // u = b*NN + n
        int c = (cellof(p[2]) * G + cellof(p[1])) * G + cellof(p[0]);
        int r = atomicAdd(&g_cnt[BB * NC + b * NC + c], 1);
        g_cell[t] = c;  g_rank[t] = r;
    }
}

// Exclusive prefix over 4096 cells per (batch, which): 256 threads x 16 cells,
// warp shfl scan + one smem round.
__global__ void k_scan() {
    __shared__ int wsum[8];
    int which = blockIdx.x & 1;          // 0 = supports, 1 = queries
    int b = blockIdx.x >> 1;
    const int* cnt = g_cnt + which * BB * NC + b * NC;
    int t = threadIdx.x, lane = t & 31, wid = t >> 5;
    int c[16];
    const int4* c4 = (const int4*)(cnt + t * 16);
    #pragma unroll
    for (int j = 0; j < 4; j++) {
        int4 v = c4[j];
        c[4*j+0] = v.x; c[4*j+1] = v.y; c[4*j+2] = v.z; c[4*j+3] = v.w;
    }
    int s = 0;
    #pragma unroll
    for (int j = 0; j < 16; j++) s += c[j];
    int inc = s;
    #pragma unroll
    for (int o = 1; o < 32; o <<= 1) {
        int y = __shfl_up_sync(0xffffffffu, inc, o);
        if (lane >= o) inc += y;
    }
    if (lane == 31) wsum[wid] = inc;
    __syncthreads();
    if (wid == 0) {
        int wv = (lane < 8) ? wsum[lane] : 0;
        int winc = wv;
        #pragma unroll
        for (int o = 1; o < 8; o <<= 1) {
            int y = __shfl_up_sync(0xffffffffu, winc, o);
            if (lane >= o) winc += y;
        }
        if (lane < 8) wsum[lane] = winc - wv;   // exclusive warp offsets
    }
    __syncthreads();
    int e = wsum[wid] + (inc - s);              // exclusive prefix for this thread
    int* start = which ? (g_qstart + b * NC) : (g_sstart + b * SSTRIDE);
    #pragma unroll
    for (int j = 0; j < 16; j++) { start[t * 16 + j] = e; e += c[j]; }
    if (which == 0 && t == 255) {
        start[NC] = e; start[NC+1] = e; start[NC+2] = e; start[NC+3] = e;
    }
}

// Atomic-free scatter: pos = start[cell] + rank.
__global__ void k_scatter(const float* __restrict__ xyzs, const float* __restrict__ xyzq) {
    int t = blockIdx.x * blockDim.x + threadIdx.x;
    if (t < BB * MM) {
        int b = t >> 12, m = t & (MM - 1);
        const float* p = xyzs + (size_t)t * 3;
        float x = p[0], y = p[1], z = p[2];
        int pos = g_sstart[b * SSTRIDE + g_cell[t]] + g_rank[t];
        g_spts[b * MM + pos] = make_float4(x, y, z, x*x + y*y + z*z);
        g_sidx[b * MM + pos] = m;
    } else if (t < BB * (MM + NN)) {
        int u = t - BB * MM;
        int b = u >> 14, n = u & (NN - 1);
        const float* p = xyzq + (size_t)u * 3;
        float x = p[0], y = p[1], z = p[2];
        int pos = g_qstart[b * NC + g_cell[t]] + g_rank[t];
        g_qpts[b * NN + pos] = make_float4(x, y, z, __int_as_float(n));
    }
}

// ---------------- Kernel A: transpose feature (B,C,N) -> (B,N,C) ----------------
__global__ void transpose_kernel(const float* __restrict__ feat) {
    __shared__ float tile[32][33];
    int b  = blockIdx.z;
    int n0 = blockIdx.x * 32;
    int c0 = blockIdx.y * 32;
    int tx = threadIdx.x, ty = threadIdx.y;   // 32 x 8
    const float* fb = feat + (size_t)b * CC * NN;
    #pragma unroll
    for (int i = 0; i < 32; i += 8)
        tile[ty + i][tx] = fb[(size_t)(c0 + ty + i) * NN + n0 + tx];
    __syncthreads();
    float* ft = g_featT + (size_t)b * NN * CC;
    #pragma unroll
    for (int i = 0; i < 32; i += 8)
        ft[(size_t)(n0 + ty + i) * CC + c0 + tx] = tile[tx][ty + i];
}

// ---------------- Kernel B: pooled[b,m,c] = max_k featT[b, idx[b,m,k], c] ----------------
__global__ void pool_kernel(const int* __restrict__ pool_idx) {
    int b = blockIdx.y;
    int m = blockIdx.x;
    int c = threadIdx.x;  // 128
    __shared__ int sidx[KK];
    if (threadIdx.x < KK)
        sidx[threadIdx.x] = pool_idx[((size_t)b * MM + m) * KK + threadIdx.x];
    __syncthreads();
    const float* fb = g_featT + (size_t)b * NN * CC;
    float v = -INFINITY;
    #pragma unroll
    for (int k = 0; k < KK; k++)
        v = fmaxf(v, fb[(size_t)sidx[k] * CC + c]);
    g_pooled[((size_t)b * MM + m) * CC + c] = v;
}

// ---------------- Kernel C: exact 3-NN via uniform grid, expanding shells ----------------
// SMEM: spts float4[4096] (64KB) | sstart int[4104] | sidx int[4096]
#define KNN_SMEM (65536 + SSTRIDE*4 + 16384)

__global__ __launch_bounds__(256) void knn_kernel() {
    extern __shared__ char sh[];
    float4* spts   = (float4*)sh;
    int*    sstart = (int*)(sh + 65536);
    int*    sidx   = (int*)(sh + 65536 + SSTRIDE*4);

    int b = blockIdx.y;
    for (int i = threadIdx.x; i < MM; i += 256)
        spts[i] = g_spts[b * MM + i];
    {
        const int4* src = (const int4*)(g_sidx + b * MM);
        int4* dst = (int4*)sidx;
        for (int i = threadIdx.x; i < MM / 4; i += 256) dst[i] = src[i];
        const int4* ss = (const int4*)(g_sstart + b * SSTRIDE);
        int4* sd = (int4*)sstart;
        for (int i = threadIdx.x; i < SSTRIDE / 4; i += 256) sd[i] = ss[i];
    }
    __syncthreads();

    int t = blockIdx.x * 256 + threadIdx.x;
    float4 qp = g_qpts[b * NN + t];
    float qx = qp.x, qy = qp.y, qz = qp.z;
    int   n  = __float_as_int(qp.w);
    float qn = qx*qx + qy*qy + qz*qz;
    int ci = cellof(qx), cj = cellof(qy), ck = cellof(qz);

    const float h = 1.0f / (float)G;
    float d0 = 1e30f, d1 = 1e30f, d2 = 1e30f;
    int   i0 = 0,     i1 = 0,     i2 = 0;

#define INSERT(dv, mv)                                              \
    do {                                                            \
        if ((dv) < d0)      { d2 = d1; i2 = i1; d1 = d0; i1 = i0;   \
                              d0 = (dv); i0 = (mv); }               \
        else if ((dv) < d1) { d2 = d1; i2 = i1;                     \
                              d1 = (dv); i1 = (mv); }               \
        else                { d2 = (dv); i2 = (mv); }               \
    } while (0)

#define SCAN_SPAN(cs, ce)                                           \
    for (int p = (cs); p < (ce); p++) {                             \
        float4 sp = spts[p];                                        \
        float dd = (qn + sp.w)                                      \
                 - 2.0f * (qx*sp.x + qy*sp.y + qz*sp.z);            \
        if (dd < d2) { int mi = sidx[p]; INSERT(dd, mi); }          \
    }

    for (int r = 0; r < G; r++) {
        int zlo = ck - r < 0 ? 0 : ck - r;
        int zhi = ck + r > G - 1 ? G - 1 : ck + r;
        for (int z = zlo; z <= zhi; z++) {
            bool zface = (z - ck == r) || (ck - z == r);
            int ylo = cj - r < 0 ? 0 : cj - r;
            int yhi = cj + r > G - 1 ? G - 1 : cj + r;
            for (int y = ylo; y <= yhi; y++) {
                bool face = zface || (y - cj == r) || (cj - y == r);
                int rowbase = (z * G + y) * G;
                if (face) {
                    int x0 = ci - r < 0 ? 0 : ci - r;
                    int x1 = ci + r > G - 1 ? G - 1 : ci + r;
                    int cs = sstart[rowbase + x0];
                    int ce = sstart[rowbase + x1 + 1];
                    SCAN_SPAN(cs, ce);
                } else {
                    int xa = ci - r;
                    if (xa >= 0) {
                        int cc0 = rowbase + xa;
                        SCAN_SPAN(sstart[cc0], sstart[cc0 + 1]);
                    }
                    int xb = ci + r;
                    if (xb <= G - 1) {
                        int cc1 = rowbase + xb;
                        SCAN_SPAN(sstart[cc1], sstart[cc1 + 1]);
                    }
                }
            }
        }
        if (d2 < 1e30f) {
            float bl = (ci - r > 0)     ? qx - (float)(ci - r) * h     : 1e30f;
            float br = (ci + r < G - 1) ? (float)(ci + r + 1) * h - qx : 1e30f;
            float bd = (cj - r > 0)     ? qy - (float)(cj - r) * h     : 1e30f;
            float bu = (cj + r < G - 1) ? (float)(cj + r + 1) * h - qy : 1e30f;
            float bn = (ck - r > 0)     ? qz - (float)(ck - r) * h     : 1e30f;
            float bf = (ck + r < G - 1) ? (float)(ck + r + 1) * h - qz : 1e30f;
            float bound = fminf(fminf(fminf(bl, br), fminf(bd, bu)), fminf(bn, bf));
            if (bound * bound >= d2 + 1e-5f) break;
        }
    }
#undef SCAN_SPAN
#undef INSERT

    float r0 = 1.0f / (d0 + 1e-8f);
    float r1 = 1.0f / (d1 + 1e-8f);
    float r2 = 1.0f / (d2 + 1e-8f);
    float rs = 1.0f / (r0 + r1 + r2);
    int base = (b * NN + n) * 3;
    g_knn[base + 0] = i0;  g_knn[base + 1] = i1;  g_knn[base + 2] = i2;
    g_wgt[base + 0] = r0 * rs;  g_wgt[base + 1] = r1 * rs;  g_wgt[base + 2] = r2 * rs;
}

// ---------------- Kernel D: out[b,c,n] = sum_j pooled[b, knn_j(n), c] * w_j(n) ----------------
__global__ __launch_bounds__(256) void interp_kernel(float* __restrict__ out) {
    __shared__ float tile[32][129];
    int b  = blockIdx.y;
    int n0 = blockIdx.x * 32;
    int t  = threadIdx.x;
    int c4  = t & 31;
    int nlo = t >> 5;

    const float* pb = g_pooled + (size_t)b * MM * CC;

    #pragma unroll
    for (int i = 0; i < 4; i++) {
        int nl = nlo + 8 * i;
        int n  = n0 + nl;
        int base = (b * NN + n) * 3;
        int j0 = g_knn[base + 0], j1 = g_knn[base + 1], j2 = g_knn[base + 2];
        float w0 = g_wgt[base + 0], w1 = g_wgt[base + 1], w2 = g_wgt[base + 2];
        const float4* p0 = (const float4*)(pb + (size_t)j0 * CC);
        const float4* p1 = (const float4*)(pb + (size_t)j1 * CC);
        const float4* p2 = (const float4*)(pb + (size_t)j2 * CC);
        float4 a = p0[c4], bb = p1[c4], cc = p2[c4];
        tile[nl][4 * c4 + 0] = w0 * a.x + w1 * bb.x + w2 * cc.x;
        tile[nl][4 * c4 + 1] = w0 * a.y + w1 * bb.y + w2 * cc.y;
        tile[nl][4 * c4 + 2] = w0 * a.z + w1 * bb.z + w2 * cc.z;
        tile[nl][4 * c4 + 3] = w0 * a.w + w1 * bb.w + w2 * cc.w;
    }
    __syncthreads();

    float* ob = out + (size_t)b * CC * NN;
    int nl = t & 31;
    #pragma unroll
    for (int i = 0; i < 16; i++) {
        int c = (t >> 5) + 8 * i;
        ob[(size_t)c * NN + n0 + nl] = tile[nl][c];
    }
}

extern "C" void kernel_launch(void* const* d_in, const int* in_sizes, int n_in,
                              void* d_out, int out_size) {
    const float* feature  = (const float*)d_in[0];
    const int*   pool_idx = (const int*)  d_in[1];
    const float* xyzq     = (const float*)d_in[2];
    const float* xyzs     = (const float*)d_in[3];
    float* out = (float*)d_out;

    static void* p_cnt = nullptr;
    if (!p_cnt) {
        cudaGetSymbolAddress(&p_cnt, g_cnt);
        cudaFuncSetAttribute(knn_kernel, cudaFuncAttributeMaxDynamicSharedMemorySize, KNN_SMEM);
    }

    // grid build for exact 3-NN (single stream, atomic-free scatter)
    cudaMemsetAsync(p_cnt, 0, sizeof(int) * 2 * BB * NC, 0);
    k_count<<<(BB * (MM + NN) + 255) / 256, 256>>>(xyzs, xyzq);
    k_scan<<<2 * BB, 256>>>();
    k_scatter<<<(BB * (MM + NN) + 255) / 256, 256>>>(xyzs, xyzq);

    // feature path
    transpose_kernel<<<dim3(NN / 32, CC / 32, BB), dim3(32, 8)>>>(feature);
    pool_kernel<<<dim3(MM, BB), CC>>>(pool_idx);

    // knn + interpolation
    knn_kernel<<<dim3(NN / 256, BB), 256, KNN_SMEM>>>();
    interp_kernel<<<dim3(NN / 32, BB), 256>>>(out);
}

// round 6
// speedup vs baseline: 1.3488x; 1.0800x over previous
#include <cuda_runtime.h>
#include <math.h>

// Problem constants
#define BB 4
#define CC 128
#define NN 16384
#define MM 4096
#define KK 16
#define G  16
#define NC (G*G*G)       // 4096 cells
#define SSTRIDE 4104     // padded (NC+1), int4/ushort-vec friendly

// Scratch (allocation-free rule: __device__ globals)
__device__ float  g_featT[BB * NN * CC];    // (B,N,C)
__device__ float  g_pooled[BB * MM * CC];   // (B,M,C)
__device__ int4   g_knni[BB * NN];          // packed neighbor indices
__device__ float4 g_knnw[BB * NN];          // packed weights

// Uniform-grid structures (per batch). Counters fused for one memset.
__device__ int            g_cnt[2 * BB * NC];
__device__ int            g_sstart[BB * SSTRIDE];
__device__ unsigned short g_sstart16[BB * SSTRIDE];
__device__ int            g_qstart[BB * NC];
__device__ int            g_cell[BB * (MM + NN)];
__device__ int            g_rank[BB * (MM + NN)];
__device__ float4         g_spts[BB * MM];          // x,y,z,|s|^2 (cell-sorted)
__device__ unsigned short g_sidx16[BB * MM];        // original support index
__device__ float4         g_qpts[BB * NN];          // x,y,z,bitcast(query idx)

__device__ __forceinline__ int cellof(float v) {
    int c = (int)(v * (float)G);
    return c < 0 ? 0 : (c > G - 1 ? G - 1 : c);
}

// ================= K1: count (blocks 0..319)  ∪  transpose (rest) =================
#define COUNT_BLOCKS ((BB * (MM + NN) + 255) / 256)   // 320

__global__ __launch_bounds__(256) void k1_count_transpose(
        const float* __restrict__ feat,
        const float* __restrict__ xyzs, const float* __restrict__ xyzq) {
    __shared__ float tile[64][65];
    if (blockIdx.x < COUNT_BLOCKS) {
        int t = blockIdx.x * 256 + threadIdx.x;
        if (t < BB * MM) {
            int b = t >> 12;
            const float* p = xyzs + (size_t)t * 3;
            int c = (cellof(p[2]) * G + cellof(p[1])) * G + cellof(p[0]);
            int r = atomicAdd(&g_cnt[b * NC + c], 1);
            g_cell[t] = c;  g_rank[t] = r;
        } else if (t < BB * (MM + NN)) {
            int u = t - BB * MM;
            int b = u >> 14;
            const float* p = xyzq + (size_t)u * 3;
            int c = (cellof(p[2]) * G + cellof(p[1])) * G + cellof(p[0]);
            int r = atomicAdd(&g_cnt[BB * NC + b * NC + c], 1);
            g_cell[t] = c;  g_rank[t] = r;
        }
        return;
    }
    // transpose: 64x64 tile, float4 both sides
    int tb = blockIdx.x - COUNT_BLOCKS;
    int b  = tb >> 9;              // 512 tiles per batch
    int rem = tb & 511;
    int cblk = rem >> 8;           // 0..1  (c-tile of 64)
    int nblk = rem & 255;          // 0..255 (n-tile of 64)
    int n0 = nblk * 64, c0 = cblk * 64;
    int t = threadIdx.x;
    int q = t & 15;                // n-quad
    int r = t >> 4;                // 16 rows per pass
    const float* fb = feat + (size_t)b * CC * NN;
    #pragma unroll
    for (int i = 0; i < 4; i++) {
        int c = r + 16 * i;
        float4 v = *(const float4*)(fb + (size_t)(c0 + c) * NN + n0 + 4 * q);
        tile[c][4*q+0] = v.x; tile[c][4*q+1] = v.y;
        tile[c][4*q+2] = v.z; tile[c][4*q+3] = v.w;
    }
    __syncthreads();
    float* ft = g_featT + (size_t)b * NN * CC;
    #pragma unroll
    for (int i = 0; i < 4; i++) {
        int n = r + 16 * i;
        float4 w = make_float4(tile[4*q+0][n], tile[4*q+1][n],
                               tile[4*q+2][n], tile[4*q+3][n]);
        *(float4*)(ft + (size_t)(n0 + n) * CC + c0 + 4 * q) = w;
    }
}

// ================= K2: scan (blocks 0..7)  ∪  pool (rest, 2 m per block) =================
__global__ __launch_bounds__(256) void k2_scan_pool(const int* __restrict__ pool_idx) {
    __shared__ int wsum[8];
    __shared__ int sidx[2][KK];
    int t = threadIdx.x;
    if (blockIdx.x < 8) {
        int which = blockIdx.x & 1;          // 0 = supports, 1 = queries
        int b = blockIdx.x >> 1;
        const int* cnt = g_cnt + which * BB * NC + b * NC;
        int lane = t & 31, wid = t >> 5;
        int c[16];
        const int4* c4 = (const int4*)(cnt + t * 16);
        #pragma unroll
        for (int j = 0; j < 4; j++) {
            int4 v = c4[j];
            c[4*j+0] = v.x; c[4*j+1] = v.y; c[4*j+2] = v.z; c[4*j+3] = v.w;
        }
        int s = 0;
        #pragma unroll
        for (int j = 0; j < 16; j++) s += c[j];
        int inc = s;
        #pragma unroll
        for (int o = 1; o < 32; o <<= 1) {
            int y = __shfl_up_sync(0xffffffffu, inc, o);
            if (lane >= o) inc += y;
        }
        if (lane == 31) wsum[wid] = inc;
        __syncthreads();
        if (wid == 0) {
            int wv = (lane < 8) ? wsum[lane] : 0;
            int winc = wv;
            #pragma unroll
            for (int o = 1; o < 8; o <<= 1) {
                int y = __shfl_up_sync(0xffffffffu, winc, o);
                if (lane >= o) winc += y;
            }
            if (lane < 8) wsum[lane] = winc - wv;
        }
        __syncthreads();
        int e = wsum[wid] + (inc - s);
        if (which == 0) {
            int* start = g_sstart + b * SSTRIDE;
            unsigned short* st16 = g_sstart16 + b * SSTRIDE;
            #pragma unroll
            for (int j = 0; j < 16; j++) {
                start[t * 16 + j] = e; st16[t * 16 + j] = (unsigned short)e;
                e += c[j];
            }
            if (t == 255) {
                for (int j = 0; j < 8; j++) {
                    start[NC + j] = e; st16[NC + j] = (unsigned short)e;
                }
            }
        } else {
            int* start = g_qstart + b * NC;
            #pragma unroll
            for (int j = 0; j < 16; j++) { start[t * 16 + j] = e; e += c[j]; }
        }
        return;
    }
    // pool: 2 m per block
    int pb = blockIdx.x - 8;
    int b  = pb >> 11;             // 2048 blocks per batch
    int m  = ((pb & 2047) << 1) + (t >> 7);
    int c  = t & 127;
    int half = t >> 7;
    if (c < KK)
        sidx[half][c] = pool_idx[((size_t)b * MM + m) * KK + c];
    __syncthreads();
    const float* fb = g_featT + (size_t)b * NN * CC;
    float v = -INFINITY;
    #pragma unroll
    for (int k = 0; k < KK; k++)
        v = fmaxf(v, fb[(size_t)sidx[half][k] * CC + c]);
    g_pooled[((size_t)b * MM + m) * CC + c] = v;
}

// ================= scatter: atomic-free, pos = start[cell] + rank =================
__global__ __launch_bounds__(256) void k_scatter(const float* __restrict__ xyzs,
                                                 const float* __restrict__ xyzq) {
    int t = blockIdx.x * blockDim.x + threadIdx.x;
    if (t < BB * MM) {
        int b = t >> 12, m = t & (MM - 1);
        const float* p = xyzs + (size_t)t * 3;
        float x = p[0], y = p[1], z = p[2];
        int pos = g_sstart[b * SSTRIDE + g_cell[t]] + g_rank[t];
        g_spts[b * MM + pos] = make_float4(x, y, z, x*x + y*y + z*z);
        g_sidx16[b * MM + pos] = (unsigned short)m;
    } else if (t < BB * (MM + NN)) {
        int u = t - BB * MM;
        int b = u >> 14, n = u & (NN - 1);
        const float* p = xyzq + (size_t)u * 3;
        float x = p[0], y = p[1], z = p[2];
        int pos = g_qstart[b * NC + g_cell[t]] + g_rank[t];
        g_qpts[b * NN + pos] = make_float4(x, y, z, __int_as_float(n));
    }
}

// ================= knn: exact 3-NN via uniform grid, expanding shells =================
// SMEM: spts float4[4096] (64KB) | sstart16 ushort[4104] | sidx16 ushort[4096]
#define OFF_SSTART 65536
#define OFF_SIDX   (65536 + SSTRIDE * 2)
#define KNN_SMEM   (OFF_SIDX + MM * 2)

__global__ __launch_bounds__(256) void knn_kernel() {
    extern __shared__ char sh[];
    float4*         spts   = (float4*)sh;
    unsigned short* sstart = (unsigned short*)(sh + OFF_SSTART);
    unsigned short* sidx   = (unsigned short*)(sh + OFF_SIDX);

    int b = blockIdx.y;
    for (int i = threadIdx.x; i < MM; i += 256)
        spts[i] = g_spts[b * MM + i];
    {
        const int4* s1 = (const int4*)(g_sstart16 + b * SSTRIDE);
        int4* d1 = (int4*)sstart;
        for (int i = threadIdx.x; i < (SSTRIDE * 2) / 16; i += 256) d1[i] = s1[i];
        const int4* s2 = (const int4*)(g_sidx16 + b * MM);
        int4* d2 = (int4*)sidx;
        for (int i = threadIdx.x; i < (MM * 2) / 16; i += 256) d2[i] = s2[i];
    }
    __syncthreads();

    int t = blockIdx.x * 256 + threadIdx.x;
    float4 qp = g_qpts[b * NN + t];
    float qx = qp.x, qy = qp.y, qz = qp.z;
    int   n  = __float_as_int(qp.w);
    float qn = qx*qx + qy*qy + qz*qz;
    int ci = cellof(qx), cj = cellof(qy), ck = cellof(qz);

    const float h = 1.0f / (float)G;
    float d0 = 1e30f, d1 = 1e30f, d2 = 1e30f;
    int   i0 = 0,     i1 = 0,     i2 = 0;

#define INSERT(dv, mv)                                              \
    do {                                                            \
        if ((dv) < d0)      { d2 = d1; i2 = i1; d1 = d0; i1 = i0;   \
                              d0 = (dv); i0 = (mv); }               \
        else if ((dv) < d1) { d2 = d1; i2 = i1;                     \
                              d1 = (dv); i1 = (mv); }               \
        else                { d2 = (dv); i2 = (mv); }               \
    } while (0)

#define SCAN_SPAN(cs, ce)                                           \
    for (int p = (cs); p < (ce); p++) {                             \
        float4 sp = spts[p];                                        \
        float dd = (qn + sp.w)                                      \
                 - 2.0f * (qx*sp.x + qy*sp.y + qz*sp.z);            \
        if (dd < d2) { int mi = (int)sidx[p]; INSERT(dd, mi); }     \
    }

    for (int r = 0; r < G; r++) {
        int zlo = ck - r < 0 ? 0 : ck - r;
        int zhi = ck + r > G - 1 ? G - 1 : ck + r;
        for (int z = zlo; z <= zhi; z++) {
            bool zface = (z - ck == r) || (ck - z == r);
            int ylo = cj - r < 0 ? 0 : cj - r;
            int yhi = cj + r > G - 1 ? G - 1 : cj + r;
            for (int y = ylo; y <= yhi; y++) {
                bool face = zface || (y - cj == r) || (cj - y == r);
                int rowbase = (z * G + y) * G;
                if (face) {
                    int x0 = ci - r < 0 ? 0 : ci - r;
                    int x1 = ci + r > G - 1 ? G - 1 : ci + r;
                    int cs = (int)sstart[rowbase + x0];
                    int ce = (int)sstart[rowbase + x1 + 1];
                    SCAN_SPAN(cs, ce);
                } else {
                    int xa = ci - r;
                    if (xa >= 0) {
                        int cc0 = rowbase + xa;
                        SCAN_SPAN((int)sstart[cc0], (int)sstart[cc0 + 1]);
                    }
                    int xb = ci + r;
                    if (xb <= G - 1) {
                        int cc1 = rowbase + xb;
                        SCAN_SPAN((int)sstart[cc1], (int)sstart[cc1 + 1]);
                    }
                }
            }
        }
        if (d2 < 1e30f) {
            float bl = (ci - r > 0)     ? qx - (float)(ci - r) * h     : 1e30f;
            float br = (ci + r < G - 1) ? (float)(ci + r + 1) * h - qx : 1e30f;
            float bd = (cj - r > 0)     ? qy - (float)(cj - r) * h     : 1e30f;
            float bu = (cj + r < G - 1) ? (float)(cj + r + 1) * h - qy : 1e30f;
            float bn = (ck - r > 0)     ? qz - (float)(ck - r) * h     : 1e30f;
            float bf = (ck + r < G - 1) ? (float)(ck + r + 1) * h - qz : 1e30f;
            float bound = fminf(fminf(fminf(bl, br), fminf(bd, bu)), fminf(bn, bf));
            if (bound * bound >= d2 + 1e-5f) break;
        }
    }
#undef SCAN_SPAN
#undef INSERT

    float r0 = 1.0f / (d0 + 1e-8f);
    float r1 = 1.0f / (d1 + 1e-8f);
    float r2 = 1.0f / (d2 + 1e-8f);
    float rs = 1.0f / (r0 + r1 + r2);
    int bn = b * NN + n;
    g_knni[bn] = make_int4(i0, i1, i2, 0);
    g_knnw[bn] = make_float4(r0 * rs, r1 * rs, r2 * rs, 0.0f);
}

// ================= interp: out[b,c,n] = sum_j pooled[b,j,c] * w_j =================
__global__ __launch_bounds__(256) void interp_kernel(float* __restrict__ out) {
    __shared__ float tile[32][129];
    int b  = blockIdx.y;
    int n0 = blockIdx.x * 32;
    int t  = threadIdx.x;
    int c4  = t & 31;
    int nlo = t >> 5;

    const float* pb = g_pooled + (size_t)b * MM * CC;

    #pragma unroll
    for (int i = 0; i < 4; i++) {
        int nl = nlo + 8 * i;
        int n  = n0 + nl;
        int bn = b * NN + n;
        int4   jj = g_knni[bn];
        float4 ww = g_knnw[bn];
        const float4* p0 = (const float4*)(pb + (size_t)jj.x * CC);
        const float4* p1 = (const float4*)(pb + (size_t)jj.y * CC);
        const float4* p2 = (const float4*)(pb + (size_t)jj.z * CC);
        float4 a = p0[c4], bb = p1[c4], cc = p2[c4];
        tile[nl][4 * c4 + 0] = ww.x * a.x + ww.y * bb.x + ww.z * cc.x;
        tile[nl][4 * c4 + 1] = ww.x * a.y + ww.y * bb.y + ww.z * cc.y;
        tile[nl][4 * c4 + 2] = ww.x * a.z + ww.y * bb.z + ww.z * cc.z;
        tile[nl][4 * c4 + 3] = ww.x * a.w + ww.y * bb.w + ww.z * cc.w;
    }
    __syncthreads();

    float* ob = out + (size_t)b * CC * NN;
    int nl = t & 31;
    #pragma unroll
    for (int i = 0; i < 16; i++) {
        int c = (t >> 5) + 8 * i;
        ob[(size_t)c * NN + n0 + nl] = tile[nl][c];
    }
}

extern "C" void kernel_launch(void* const* d_in, const int* in_sizes, int n_in,
                              void* d_out, int out_size) {
    const float* feature  = (const float*)d_in[0];
    const int*   pool_idx = (const int*)  d_in[1];
    const float* xyzq     = (const float*)d_in[2];
    const float* xyzs     = (const float*)d_in[3];
    float* out = (float*)d_out;

    static void* p_cnt = nullptr;
    if (!p_cnt) {
        cudaGetSymbolAddress(&p_cnt, g_cnt);
        cudaFuncSetAttribute(knn_kernel, cudaFuncAttributeMaxDynamicSharedMemorySize, KNN_SMEM);
    }

    cudaMemsetAsync(p_cnt, 0, sizeof(int) * 2 * BB * NC, 0);
    k1_count_transpose<<<COUNT_BLOCKS + 2048, 256>>>(feature, xyzs, xyzq);
    k2_scan_pool<<<8 + (BB * MM / 2), 256>>>(pool_idx);
    k_scatter<<<COUNT_BLOCKS, 256>>>(xyzs, xyzq);
    knn_kernel<<<dim3(NN / 256, BB), 256, KNN_SMEM>>>();
    interp_kernel<<<dim3(NN / 32, BB), 256>>>(out);
}

// round 8
// speedup vs baseline: 1.4209x; 1.0534x over previous
#include <cuda_runtime.h>
#include <math.h>

// Problem constants
#define BB 4
#define CC 128
#define NN 16384
#define MM 4096
#define KK 16
#define G  16
#define NC (G*G*G)       // 4096 cells
#define SSTRIDE 4104     // padded (NC+1), int4/ushort-vec friendly

// Scratch (allocation-free rule: __device__ globals)
__device__ float  g_featT[BB * NN * CC];    // (B,N,C)
__device__ float  g_pooled[BB * MM * CC];   // (B,M,C)
__device__ int4   g_knni[BB * NN];          // packed neighbor indices
__device__ float4 g_knnw[BB * NN];          // packed weights

// Uniform-grid structures (per batch). Counters fused for one memset.
__device__ int            g_cnt[2 * BB * NC];
__device__ int            g_sstart[BB * SSTRIDE];
__device__ unsigned short g_sstart16[BB * SSTRIDE];
__device__ int            g_qstart[BB * NC];
__device__ int            g_cell[BB * (MM + NN)];
__device__ int            g_rank[BB * (MM + NN)];
__device__ float4         g_spts[BB * MM];          // x,y,z,|s|^2 (cell-sorted)
__device__ unsigned short g_sidx16[BB * MM];        // original support index
__device__ float4         g_qpts[BB * NN];          // x,y,z,bitcast(query idx)

__device__ __forceinline__ int cellof(float v) {
    int c = (int)(v * (float)G);
    return c < 0 ? 0 : (c > G - 1 ? G - 1 : c);
}

// ================= K1: count (blocks 0..319)  ∪  transpose (rest) =================
#define COUNT_BLOCKS ((BB * (MM + NN) + 255) / 256)   // 320

__global__ __launch_bounds__(256) void k1_count_transpose(
        const float* __restrict__ feat,
        const float* __restrict__ xyzs, const float* __restrict__ xyzq) {
    __shared__ float tile[64][65];
    if (blockIdx.x < COUNT_BLOCKS) {
        int t = blockIdx.x * 256 + threadIdx.x;
        if (t < BB * MM) {
            int b = t >> 12;
            const float* p = xyzs + (size_t)t * 3;
            int c = (cellof(p[2]) * G + cellof(p[1])) * G + cellof(p[0]);
            int r = atomicAdd(&g_cnt[b * NC + c], 1);
            g_cell[t] = c;  g_rank[t] = r;
        } else if (t < BB * (MM + NN)) {
            int u = t - BB * MM;
            int b = u >> 14;
            const float* p = xyzq + (size_t)u * 3;
            int c = (cellof(p[2]) * G + cellof(p[1])) * G + cellof(p[0]);
            int r = atomicAdd(&g_cnt[BB * NC + b * NC + c], 1);
            g_cell[t] = c;  g_rank[t] = r;
        }
        return;
    }
    // transpose: 64x64 tile, float4 both sides
    int tb = blockIdx.x - COUNT_BLOCKS;
    int b  = tb >> 9;              // 512 tiles per batch
    int rem = tb & 511;
    int cblk = rem >> 8;           // 0..1  (c-tile of 64)
    int nblk = rem & 255;          // 0..255 (n-tile of 64)
    int n0 = nblk * 64, c0 = cblk * 64;
    int t = threadIdx.x;
    int q = t & 15;                // n-quad
    int r = t >> 4;                // 16 rows per pass
    const float* fb = feat + (size_t)b * CC * NN;
    #pragma unroll
    for (int i = 0; i < 4; i++) {
        int c = r + 16 * i;
        float4 v = *(const float4*)(fb + (size_t)(c0 + c) * NN + n0 + 4 * q);
        tile[c][4*q+0] = v.x; tile[c][4*q+1] = v.y;
        tile[c][4*q+2] = v.z; tile[c][4*q+3] = v.w;
    }
    __syncthreads();
    float* ft = g_featT + (size_t)b * NN * CC;
    #pragma unroll
    for (int i = 0; i < 4; i++) {
        int n = r + 16 * i;
        float4 w = make_float4(tile[4*q+0][n], tile[4*q+1][n],
                               tile[4*q+2][n], tile[4*q+3][n]);
        *(float4*)(ft + (size_t)(n0 + n) * CC + c0 + 4 * q) = w;
    }
}

// ================= K2: scan (blocks 0..7)  ∪  pool (rest, 2 m per block) =================
__global__ __launch_bounds__(256) void k2_scan_pool(const int* __restrict__ pool_idx) {
    __shared__ int wsum[8];
    __shared__ int sidx[2][KK];
    int t = threadIdx.x;
    if (blockIdx.x < 8) {
        int which = blockIdx.x & 1;          // 0 = supports, 1 = queries
        int b = blockIdx.x >> 1;
        const int* cnt = g_cnt + which * BB * NC + b * NC;
        int lane = t & 31, wid = t >> 5;
        int c[16];
        const int4* c4 = (const int4*)(cnt + t * 16);
        #pragma unroll
        for (int j = 0; j < 4; j++) {
            int4 v = c4[j];
            c[4*j+0] = v.x; c[4*j+1] = v.y; c[4*j+2] = v.z; c[4*j+3] = v.w;
        }
        int s = 0;
        #pragma unroll
        for (int j = 0; j < 16; j++) s += c[j];
        int inc = s;
        #pragma unroll
        for (int o = 1; o < 32; o <<= 1) {
            int y = __shfl_up_sync(0xffffffffu, inc, o);
            if (lane >= o) inc += y;
        }
        if (lane == 31) wsum[wid] = inc;
        __syncthreads();
        if (wid == 0) {
            int wv = (lane < 8) ? wsum[lane] : 0;
            int winc = wv;
            #pragma unroll
            for (int o = 1; o < 8; o <<= 1) {
                int y = __shfl_up_sync(0xffffffffu, winc, o);
                if (lane >= o) winc += y;
            }
            if (lane < 8) wsum[lane] = winc - wv;
        }
        __syncthreads();
        int e = wsum[wid] + (inc - s);
        if (which == 0) {
            int* start = g_sstart + b * SSTRIDE;
            unsigned short* st16 = g_sstart16 + b * SSTRIDE;
            #pragma unroll
            for (int j = 0; j < 16; j++) {
                start[t * 16 + j] = e; st16[t * 16 + j] = (unsigned short)e;
                e += c[j];
            }
            if (t == 255) {
                for (int j = 0; j < 8; j++) {
                    start[NC + j] = e; st16[NC + j] = (unsigned short)e;
                }
            }
        } else {
            int* start = g_qstart + b * NC;
            #pragma unroll
            for (int j = 0; j < 16; j++) { start[t * 16 + j] = e; e += c[j]; }
        }
        return;
    }
    // pool: 2 m per block
    int pb = blockIdx.x - 8;
    int b  = pb >> 11;             // 2048 blocks per batch
    int m  = ((pb & 2047) << 1) + (t >> 7);
    int c  = t & 127;
    int half = t >> 7;
    if (c < KK)
        sidx[half][c] = pool_idx[((size_t)b * MM + m) * KK + c];
    __syncthreads();
    const float* fb = g_featT + (size_t)b * NN * CC;
    float v = -INFINITY;
    #pragma unroll
    for (int k = 0; k < KK; k++)
        v = fmaxf(v, fb[(size_t)sidx[half][k] * CC + c]);
    g_pooled[((size_t)b * MM + m) * CC + c] = v;
}

// ================= scatter: atomic-free, pos = start[cell] + rank =================
__global__ __launch_bounds__(256) void k_scatter(const float* __restrict__ xyzs,
                                                 const float* __restrict__ xyzq) {
    int t = blockIdx.x * blockDim.x + threadIdx.x;
    if (t < BB * MM) {
        int b = t >> 12, m = t & (MM - 1);
        const float* p = xyzs + (size_t)t * 3;
        float x = p[0], y = p[1], z = p[2];
        int pos = g_sstart[b * SSTRIDE + g_cell[t]] + g_rank[t];
        g_spts[b * MM + pos] = make_float4(x, y, z, x*x + y*y + z*z);
        g_sidx16[b * MM + pos] = (unsigned short)m;
    } else if (t < BB * (MM + NN)) {
        int u = t - BB * MM;
        int b = u >> 14, n = u & (NN - 1);
        const float* p = xyzq + (size_t)u * 3;
        float x = p[0], y = p[1], z = p[2];
        int pos = g_qstart[b * NC + g_cell[t]] + g_rank[t];
        g_qpts[b * NN + pos] = make_float4(x, y, z, __int_as_float(n));
    }
}

// ================= knn: exact 3-NN via uniform grid =================
// SMEM: spts float4[4096] (64KB) | sstart16 ushort[4104] (8.2KB)
#define OFF_SSTART 65536
#define KNN_SMEM   (OFF_SSTART + SSTRIDE * 2)

__global__ __launch_bounds__(256) void knn_kernel() {
    extern __shared__ char sh[];
    float4*         spts   = (float4*)sh;
    unsigned short* sstart = (unsigned short*)(sh + OFF_SSTART);

    int b = blockIdx.y;
    for (int i = threadIdx.x; i < MM; i += 256)
        spts[i] = g_spts[b * MM + i];
    {
        const int4* s1 = (const int4*)(g_sstart16 + b * SSTRIDE);
        int4* d1 = (int4*)sstart;
        for (int i = threadIdx.x; i < (SSTRIDE * 2) / 16; i += 256) d1[i] = s1[i];
    }
    __syncthreads();

    int t = blockIdx.x * 256 + threadIdx.x;
    float4 qp = g_qpts[b * NN + t];
    float qx = qp.x, qy = qp.y, qz = qp.z;
    int   n  = __float_as_int(qp.w);
    float qn = qx*qx + qy*qy + qz*qz;
    int ci = cellof(qx), cj = cellof(qy), ck = cellof(qz);

    const float h = 1.0f / (float)G;
    float d0 = 1e30f, d1 = 1e30f, d2 = 1e30f;
    int   p0 = 0,     p1 = 0,     p2 = 0;   // positions in cell-sorted order

#define INSERT(dv, pv)                                              \
    do {                                                            \
        if ((dv) < d0)      { d2 = d1; p2 = p1; d1 = d0; p1 = p0;   \
                              d0 = (dv); p0 = (pv); }               \
        else if ((dv) < d1) { d2 = d1; p2 = p1;                     \
                              d1 = (dv); p1 = (pv); }               \
        else                { d2 = (dv); p2 = (pv); }               \
    } while (0)

#define DIST(sp) ((qn + (sp).w) - 2.0f * (qx*(sp).x + qy*(sp).y + qz*(sp).z))

#define SCAN_SPAN(cs, ce)                                           \
    {                                                               \
        int p = (cs);                                               \
        for (; p + 2 <= (ce); p += 2) {                             \
            float4 sa = spts[p];                                    \
            float4 sb = spts[p + 1];                                \
            float da = DIST(sa);                                    \
            float db = DIST(sb);                                    \
            if (fminf(da, db) < d2) {                               \
                if (da < d2) INSERT(da, p);                         \
                if (db < d2) INSERT(db, p + 1);                     \
            }                                                       \
        }                                                           \
        if (p < (ce)) {                                             \
            float4 sa = spts[p];                                    \
            float da = DIST(sa);                                    \
            if (da < d2) INSERT(da, p);                             \
        }                                                           \
    }

    // ---- fast path: whole 3x3x3 box (shells r=0 and r=1 fused), 9 row-spans ----
    {
        int zlo = ck - 1 < 0 ? 0 : ck - 1;
        int zhi = ck + 1 > G - 1 ? G - 1 : ck + 1;
        int ylo = cj - 1 < 0 ? 0 : cj - 1;
        int yhi = cj + 1 > G - 1 ? G - 1 : cj + 1;
        int xlo = ci - 1 < 0 ? 0 : ci - 1;
        int xhi = ci + 1 > G - 1 ? G - 1 : ci + 1;
        for (int z = zlo; z <= zhi; z++)
            for (int y = ylo; y <= yhi; y++) {
                int rowbase = (z * G + y) * G;
                int cs = (int)sstart[rowbase + xlo];
                int ce = (int)sstart[rowbase + xhi + 1];
                SCAN_SPAN(cs, ce);
            }
    }
    // termination bound after r=1 box
    bool done = false;
    if (d2 < 1e30f) {
        float bl = (ci - 1 > 0)     ? qx - (float)(ci - 1) * h : 1e30f;
        float br = (ci + 1 < G - 1) ? (float)(ci + 2) * h - qx : 1e30f;
        float bd = (cj - 1 > 0)     ? qy - (float)(cj - 1) * h : 1e30f;
        float bu = (cj + 1 < G - 1) ? (float)(cj + 2) * h - qy : 1e30f;
        float bn = (ck - 1 > 0)     ? qz - (float)(ck - 1) * h : 1e30f;
        float bf = (ck + 1 < G - 1) ? (float)(ck + 2) * h - qz : 1e30f;
        float bound = fminf(fminf(fminf(bl, br), fminf(bd, bu)), fminf(bn, bf));
        done = (bound * bound >= d2 + 1e-5f);
    }

    // ---- general shells r >= 2 ----
    if (!done)
    for (int r = 2; r < G; r++) {
        int zlo = ck - r < 0 ? 0 : ck - r;
        int zhi = ck + r > G - 1 ? G - 1 : ck + r;
        for (int z = zlo; z <= zhi; z++) {
            bool zface = (z - ck == r) || (ck - z == r);
            int ylo = cj - r < 0 ? 0 : cj - r;
            int yhi = cj + r > G - 1 ? G - 1 : cj + r;
            for (int y = ylo; y <= yhi; y++) {
                bool face = zface || (y - cj == r) || (cj - y == r);
                int rowbase = (z * G + y) * G;
                if (face) {
                    int x0 = ci - r < 0 ? 0 : ci - r;
                    int x1 = ci + r > G - 1 ? G - 1 : ci + r;
                    int cs = (int)sstart[rowbase + x0];
                    int ce = (int)sstart[rowbase + x1 + 1];
                    SCAN_SPAN(cs, ce);
                } else {
                    int xa = ci - r;
                    if (xa >= 0) {
                        int cc0 = rowbase + xa;
                        SCAN_SPAN((int)sstart[cc0], (int)sstart[cc0 + 1]);
                    }
                    int xb = ci + r;
                    if (xb <= G - 1) {
                        int cc1 = rowbase + xb;
                        SCAN_SPAN((int)sstart[cc1], (int)sstart[cc1 + 1]);
                    }
                }
            }
        }
        if (d2 < 1e30f) {
            float bl = (ci - r > 0)     ? qx - (float)(ci - r) * h     : 1e30f;
            float br = (ci + r < G - 1) ? (float)(ci + r + 1) * h - qx : 1e30f;
            float bd = (cj - r > 0)     ? qy - (float)(cj - r) * h     : 1e30f;
            float bu = (cj + r < G - 1) ? (float)(cj + r + 1) * h - qy : 1e30f;
            float bn = (ck - r > 0)     ? qz - (float)(ck - r) * h     : 1e30f;
            float bf = (ck + r < G - 1) ? (float)(ck + r + 1) * h - qz : 1e30f;
            float bound = fminf(fminf(fminf(bl, br), fminf(bd, bu)), fminf(bn, bf));
            if (bound * bound >= d2 + 1e-5f) break;
        }
    }
#undef SCAN_SPAN
#undef DIST
#undef INSERT

    // resolve sorted positions -> original support indices (3 L2 loads)
    const unsigned short* si = g_sidx16 + b * MM;
    int i0 = (int)si[p0], i1 = (int)si[p1], i2 = (int)si[p2];

    float r0 = 1.0f / (d0 + 1e-8f);
    float r1 = 1.0f / (d1 + 1e-8f);
    float r2 = 1.0f / (d2 + 1e-8f);
    float rs = 1.0f / (r0 + r1 + r2);
    int bn = b * NN + n;
    g_knni[bn] = make_int4(i0, i1, i2, 0);
    g_knnw[bn] = make_float4(r0 * rs, r1 * rs, r2 * rs, 0.0f);
}

// ================= interp: out[b,c,n] = sum_j pooled[b,j,c] * w_j =================
__global__ __launch_bounds__(256) void interp_kernel(float* __restrict__ out) {
    __shared__ float tile[32][129];
    int b  = blockIdx.y;
    int n0 = blockIdx.x * 32;
    int t  = threadIdx.x;
    int c4  = t & 31;
    int nlo = t >> 5;

    const float* pb = g_pooled + (size_t)b * MM * CC;

    #pragma unroll
    for (int i = 0; i < 4; i++) {
        int nl = nlo + 8 * i;
        int n  = n0 + nl;
        int bn = b * NN + n;
        int4   jj = g_knni[bn];
        float4 ww = g_knnw[bn];
        const float4* p0 = (const float4*)(pb + (size_t)jj.x * CC);
        const float4* p1 = (const float4*)(pb + (size_t)jj.y * CC);
        const float4* p2 = (const float4*)(pb + (size_t)jj.z * CC);
        float4 a = p0[c4], bb = p1[c4], cc = p2[c4];
        tile[nl][4 * c4 + 0] = ww.x * a.x + ww.y * bb.x + ww.z * cc.x;
        tile[nl][4 * c4 + 1] = ww.x * a.y + ww.y * bb.y + ww.z * cc.y;
        tile[nl][4 * c4 + 2] = ww.x * a.z + ww.y * bb.z + ww.z * cc.z;
        tile[nl][4 * c4 + 3] = ww.x * a.w + ww.y * bb.w + ww.z * cc.w;
    }
    __syncthreads();

    float* ob = out + (size_t)b * CC * NN;
    int nl = t & 31;
    #pragma unroll
    for (int i = 0; i < 16; i++) {
        int c = (t >> 5) + 8 * i;
        ob[(size_t)c * NN + n0 + nl] = tile[nl][c];
    }
}

extern "C" void kernel_launch(void* const* d_in, const int* in_sizes, int n_in,
                              void* d_out, int out_size) {
    const float* feature  = (const float*)d_in[0];
    const int*   pool_idx = (const int*)  d_in[1];
    const float* xyzq     = (const float*)d_in[2];
    const float* xyzs     = (const float*)d_in[3];
    float* out = (float*)d_out;

    static void* p_cnt = nullptr;
    if (!p_cnt) {
        cudaGetSymbolAddress(&p_cnt, g_cnt);
        cudaFuncSetAttribute(knn_kernel, cudaFuncAttributeMaxDynamicSharedMemorySize, KNN_SMEM);
    }

    cudaMemsetAsync(p_cnt, 0, sizeof(int) * 2 * BB * NC, 0);
    k1_count_transpose<<<COUNT_BLOCKS + 2048, 256>>>(feature, xyzs, xyzq);
    k2_scan_pool<<<8 + (BB * MM / 2), 256>>>(pool_idx);
    k_scatter<<<COUNT_BLOCKS, 256>>>(xyzs, xyzq);
    knn_kernel<<<dim3(NN / 256, BB), 256, KNN_SMEM>>>();
    interp_kernel<<<dim3(NN / 32, BB), 256>>>(out);
}